// round 1
// baseline (speedup 1.0000x reference)
#include <cuda_runtime.h>
#include <math.h>

#define BM   64
#define BK   64
#define DIM  2048
#define NEXP 64
#define NTOK 16384
#define NCHUNK (DIM / BK)

__device__ __forceinline__ void fma2(unsigned long long &d,
                                     unsigned long long a,
                                     unsigned long long b) {
    // packed f32x2 FMA: d = a*b + d  (elementwise on two fp32 lanes)
    asm volatile("fma.rn.f32x2 %0, %1, %2, %0;" : "+l"(d) : "l"(a), "l"(b));
}

__global__ __launch_bounds__(256, 2)
void router_kernel(const float* __restrict__ x,
                   const float* __restrict__ W,
                   const float* __restrict__ b,
                   float* __restrict__ out) {
    __shared__ __align__(16) float xs[BM][BK];          // [token][k]
    __shared__ __align__(16) float wsT[NEXP][BK + 4];   // [expert][k], +4 pad (16B-mult stride)
    __shared__ float bs[NEXP];

    const int tid  = threadIdx.x;
    const int lane = tid & 31;
    const int warp = tid >> 5;
    const int m0   = blockIdx.x * BM;

    if (tid < NEXP) bs[tid] = b[tid];

    // Accumulators: per lane, experts (lane) and (lane+32), 8 tokens each.
    // Each u64 holds two fp32 partial sums (even-k, odd-k parity).
    unsigned long long acc0[8], acc1[8];
    #pragma unroll
    for (int t = 0; t < 8; ++t) { acc0[t] = 0ull; acc1[t] = 0ull; }

    float4 xr[4], wr[4];

    auto loadX = [&](int k0) {
        #pragma unroll
        for (int i = 0; i < 4; ++i) {
            int id = tid + i * 256;
            int r = id >> 4, c4 = id & 15;
            xr[i] = *(const float4*)&x[(size_t)(m0 + r) * DIM + k0 + c4 * 4];
        }
    };
    auto storeX = [&]() {
        #pragma unroll
        for (int i = 0; i < 4; ++i) {
            int id = tid + i * 256;
            int r = id >> 4, c4 = id & 15;
            *(float4*)&xs[r][c4 * 4] = xr[i];
        }
    };
    auto loadW = [&](int k0) {
        #pragma unroll
        for (int i = 0; i < 4; ++i) {
            int id = tid + i * 256;
            int kk = id >> 4, e4 = id & 15;
            wr[i] = *(const float4*)&W[(size_t)(k0 + kk) * NEXP + e4 * 4];
        }
    };
    auto storeW = [&]() {
        #pragma unroll
        for (int i = 0; i < 4; ++i) {
            int id = tid + i * 256;
            int kk = id >> 4, e4 = id & 15;
            wsT[e4 * 4 + 0][kk] = wr[i].x;
            wsT[e4 * 4 + 1][kk] = wr[i].y;
            wsT[e4 * 4 + 2][kk] = wr[i].z;
            wsT[e4 * 4 + 3][kk] = wr[i].w;
        }
    };

    loadX(0); loadW(0);
    storeX(); storeW();
    __syncthreads();

    const int tw = warp * 8;

    for (int c = 0; c < NCHUNK; ++c) {
        if (c + 1 < NCHUNK) { loadX((c + 1) * BK); loadW((c + 1) * BK); }

        #pragma unroll 4
        for (int k4 = 0; k4 < BK; k4 += 4) {
            ulonglong2 w0 = *(const ulonglong2*)&wsT[lane][k4];
            ulonglong2 w1 = *(const ulonglong2*)&wsT[lane + 32][k4];
            #pragma unroll
            for (int t = 0; t < 8; ++t) {
                ulonglong2 xv = *(const ulonglong2*)&xs[tw + t][k4];
                fma2(acc0[t], xv.x, w0.x);
                fma2(acc0[t], xv.y, w0.y);
                fma2(acc1[t], xv.x, w1.x);
                fma2(acc1[t], xv.y, w1.y);
            }
        }
        __syncthreads();
        if (c + 1 < NCHUNK) { storeX(); storeW(); __syncthreads(); }
    }

    // Epilogue: bias + softmax + top-2 per token (warp-wide)
    const float NEG = __int_as_float(0xff800000); // -inf
    #pragma unroll
    for (int t = 0; t < 8; ++t) {
        const int gt = m0 + tw + t;
        unsigned long long a0 = acc0[t], a1 = acc1[t];
        float l0 = __uint_as_float((unsigned)a0) +
                   __uint_as_float((unsigned)(a0 >> 32)) + bs[lane];
        float l1 = __uint_as_float((unsigned)a1) +
                   __uint_as_float((unsigned)(a1 >> 32)) + bs[lane + 32];

        // top-1 (tie-break: lowest expert index, matching jax.lax.top_k)
        float v = (l0 >= l1) ? l0 : l1;
        int   i = (l0 >= l1) ? lane : lane + 32;
        #pragma unroll
        for (int off = 16; off; off >>= 1) {
            float ov = __shfl_xor_sync(0xffffffffu, v, off);
            int   oi = __shfl_xor_sync(0xffffffffu, i, off);
            if (ov > v || (ov == v && oi < i)) { v = ov; i = oi; }
        }
        const float v1 = v; const int i1 = i;

        // top-2: exclude winner
        float la = (lane      == i1) ? NEG : l0;
        float lb = (lane + 32 == i1) ? NEG : l1;
        v = (la >= lb) ? la : lb;
        i = (la >= lb) ? lane : lane + 32;
        #pragma unroll
        for (int off = 16; off; off >>= 1) {
            float ov = __shfl_xor_sync(0xffffffffu, v, off);
            int   oi = __shfl_xor_sync(0xffffffffu, i, off);
            if (ov > v || (ov == v && oi < i)) { v = ov; i = oi; }
        }
        const float v2 = v; const int i2 = i;

        // softmax denominator (stabilized by true max v1)
        float s = expf(l0 - v1) + expf(l1 - v1);
        #pragma unroll
        for (int off = 16; off; off >>= 1)
            s += __shfl_xor_sync(0xffffffffu, s, off);

        if (lane == 0) {
            out[(size_t)gt * 2 + 0] = (float)i1;
            out[(size_t)gt * 2 + 1] = (float)i2;
            out[(size_t)2 * NTOK + gt * 2 + 0] = 1.0f / s;
            out[(size_t)2 * NTOK + gt * 2 + 1] = expf(v2 - v1) / s;
        }
    }
}

extern "C" void kernel_launch(void* const* d_in, const int* in_sizes, int n_in,
                              void* d_out, int out_size) {
    const float* x = (const float*)d_in[0];
    const float* W = (const float*)d_in[1];
    const float* b = (const float*)d_in[2];
    float* out = (float*)d_out;
    router_kernel<<<NTOK / BM, 256>>>(x, W, b, out);
}